// round 15
// baseline (speedup 1.0000x reference)
#include <cuda_runtime.h>
#include <math.h>

#define BATCH 16384
#define KDIM 128
#define CLS 32
#define PL 132             // sS pitch (%4==0)
#define PW 68              // 64-block pitch (%4==0)
#define P3 36              // 32-block pitch (%4==0)
#define PT 33              // k_tr staging pitch (conflict-free)
#define RCHUNK 8
#define RPC (BATCH / RCHUNK)   // 2048
#define MSZ (KDIM * KDIM)      // 16384

// ---------------- scratch (device globals: allocation-free) ----------------
__device__ float g_sum[CLS * KDIM];
__device__ int   g_cnt[CLS];
__device__ int   g_first[CLS];
__device__ float g_G[CLS * MSZ];       // lower triangle valid; upper stays 0
__device__ float g_inv[CLS * MSZ];
__device__ float g_mu[CLS * KDIM];
__device__ float g_w[CLS * KDIM];      // w_c = inv_c · mu_c
__device__ float g_ld2[CLS];
__device__ float g_trI[CLS];           // tr(inv_c)
__device__ float g_pjj[CLS];           // mu_c^T inv_c mu_c
__device__ float g_TR[CLS * CLS];      // <G_i, inv_j>/n_i

// ---------------- K0: zero all scratch + output ----------------
__global__ void k_init(float* out) {
    int i = blockIdx.x * blockDim.x + threadIdx.x;
    if (i < CLS * MSZ) g_G[i] = 0.0f;
    if (i < CLS * KDIM) g_sum[i] = 0.0f;
    if (i < CLS * CLS) g_TR[i] = 0.0f;
    if (i < CLS) { g_cnt[i] = 0; g_first[i] = BATCH; }
    if (i == 0) out[0] = 0.0f;
}

// ------- K1: per-class Gram (atomic, lower tri) + fused sums/count/first ---
// (inner loop: proven R9 scalar-broadcast form — do not vectorize)
__global__ __launch_bounds__(256) void k_scatter(const float* __restrict__ feat,
                                                 const int* __restrict__ lab) {
    const int c = blockIdx.y;
    const int chunk = blockIdx.x;
    const int R0 = chunk * RPC;
    __shared__ int s_idx[RPC];
    __shared__ int s_n, s_min;
    __shared__ __align__(16) float s_x[16][KDIM];
    const int tid = threadIdx.x;
    if (tid == 0) { s_n = 0; s_min = BATCH; }
    __syncthreads();

    for (int r = R0 + tid; r < R0 + RPC; r += 256) {
        if (lab[r] == c) {
            int p = atomicAdd(&s_n, 1);
            s_idx[p] = r;
            atomicMin(&s_min, r);
        }
    }
    __syncthreads();
    const int n = s_n;
    if (n == 0) return;

    float acc[8][8];
#pragma unroll
    for (int u = 0; u < 8; u++)
#pragma unroll
        for (int v = 0; v < 8; v++) acc[u][v] = 0.0f;
    float csum = 0.0f;

    const int ty = tid >> 4, tx = tid & 15;

    for (int t = 0; t < n; t += 16) {
        int m = min(16, n - t);
        for (int i = tid; i < m * 32; i += 256) {
            int rr = i >> 5, q = i & 31;
            ((float4*)s_x[rr])[q] =
                ((const float4*)(feat + (size_t)s_idx[t + rr] * KDIM))[q];
        }
        __syncthreads();
        if (tid < KDIM)
            for (int e = 0; e < m; e++) csum += s_x[e][tid];
        for (int e = 0; e < m; e++) {
            float a[8], b[8];
#pragma unroll
            for (int u = 0; u < 8; u++) { a[u] = s_x[e][ty * 8 + u]; b[u] = s_x[e][tx * 8 + u]; }
#pragma unroll
            for (int u = 0; u < 8; u++)
#pragma unroll
                for (int v = 0; v < 8; v++) acc[u][v] = fmaf(a[u], b[v], acc[u][v]);
        }
        __syncthreads();
    }

    // lower triangle only (col <= row) — halves global atomic traffic
    float* G = g_G + (size_t)c * MSZ;
    if (tx <= ty) {
#pragma unroll
        for (int u = 0; u < 8; u++)
#pragma unroll
            for (int v = 0; v < 8; v++) {
                int row = ty * 8 + u, col = tx * 8 + v;
                if (col <= row)
                    atomicAdd(&G[row * KDIM + col], acc[u][v]);
            }
    }

    if (tid < KDIM) atomicAdd(&g_sum[c * KDIM + tid], csum);
    if (tid == 0) { atomicAdd(&g_cnt[c], n); atomicMin(&g_first[c], s_min); }
}

// ---------------- warp Gauss-Jordan inverse of SPD 32x32 (in-place) --------
__device__ __forceinline__ void gj32(float* M, int P, float* ldacc) {
    const int lane = threadIdx.x & 31;
    float y[32];
#pragma unroll
    for (int m = 0; m < 32; m++) y[m] = M[lane * P + m];
    float ld = 0.0f;
#pragma unroll
    for (int j = 0; j < 32; j++) {
        float pj = __shfl_sync(0xffffffffu, y[j], j);
        float r = __fdividef(1.0f, pj);
        float c = y[j];
        if (lane == j) {
            ld = log2f(pj);
#pragma unroll
            for (int m = 0; m < 32; m++) y[m] *= r;
            y[j] = r;
        }
#pragma unroll
        for (int m = 0; m < 32; m++) {
            float rowj = __shfl_sync(0xffffffffu, y[m], j);
            if (lane != j && m != j) y[m] -= c * rowj;
        }
        if (lane != j) y[j] = -c * r;
    }
#pragma unroll
    for (int m = 0; m < 32; m++) M[lane * P + m] = y[m];
#pragma unroll
    for (int o = 16; o; o >>= 1) ld += __shfl_xor_sync(0xffffffffu, ld, o);
    if (lane == 0) *ldacc += ld;
}

// ------ 64-GEMM (256 thr, 4x4 tiles): O = c0s*C0 + sgn*op(P)·Q -------------
template<bool TRA>
__device__ __forceinline__ void sgemm64(const float* __restrict__ P, int pp,
                                        const float* __restrict__ Q, int pq,
                                        float* __restrict__ O, int po,
                                        const float* __restrict__ C0, int pc,
                                        float c0s, float sgn) {
    const int r0 = (threadIdx.x >> 4) * 4;
    const int c0 = (threadIdx.x & 15) * 4;
    float acc[4][4];
#pragma unroll
    for (int u = 0; u < 4; u++)
#pragma unroll
        for (int v = 0; v < 4; v++) acc[u][v] = 0.0f;
#pragma unroll 4
    for (int m = 0; m < 64; m++) {
        float4 b = *(const float4*)&Q[m * pq + c0];
        float a[4];
        if (TRA) {
            float4 t = *(const float4*)&P[m * pp + r0];
            a[0] = t.x; a[1] = t.y; a[2] = t.z; a[3] = t.w;
        } else {
#pragma unroll
            for (int u = 0; u < 4; u++) a[u] = P[(r0 + u) * pp + m];
        }
#pragma unroll
        for (int u = 0; u < 4; u++) {
            acc[u][0] = fmaf(a[u], b.x, acc[u][0]);
            acc[u][1] = fmaf(a[u], b.y, acc[u][1]);
            acc[u][2] = fmaf(a[u], b.z, acc[u][2]);
            acc[u][3] = fmaf(a[u], b.w, acc[u][3]);
        }
    }
#pragma unroll
    for (int u = 0; u < 4; u++) {
        float4 o = make_float4(sgn * acc[u][0], sgn * acc[u][1],
                               sgn * acc[u][2], sgn * acc[u][3]);
        if (C0) {
            float4 cc = *(const float4*)&C0[(r0 + u) * pc + c0];
            o.x += c0s * cc.x; o.y += c0s * cc.y;
            o.z += c0s * cc.z; o.w += c0s * cc.w;
        }
        *(float4*)&O[(r0 + u) * po + c0] = o;
    }
}

// ------ 32-GEMM (256 thr, 2x2 tiles) ----------------------------------------
template<bool TRA>
__device__ __forceinline__ void sgemm32(const float* __restrict__ P, int pp,
                                        const float* __restrict__ Q, int pq,
                                        float* __restrict__ O, int po,
                                        const float* __restrict__ C0, int pc,
                                        float c0s, float sgn) {
    const int r0 = (threadIdx.x >> 4) * 2;
    const int c0 = (threadIdx.x & 15) * 2;
    float acc[2][2] = {{0.f, 0.f}, {0.f, 0.f}};
#pragma unroll 8
    for (int m = 0; m < 32; m++) {
        float2 b = *(const float2*)&Q[m * pq + c0];
        float a0 = TRA ? P[m * pp + r0]     : P[r0 * pp + m];
        float a1 = TRA ? P[m * pp + r0 + 1] : P[(r0 + 1) * pp + m];
        acc[0][0] = fmaf(a0, b.x, acc[0][0]); acc[0][1] = fmaf(a0, b.y, acc[0][1]);
        acc[1][0] = fmaf(a1, b.x, acc[1][0]); acc[1][1] = fmaf(a1, b.y, acc[1][1]);
    }
#pragma unroll
    for (int u = 0; u < 2; u++) {
        float2 o = make_float2(sgn * acc[u][0], sgn * acc[u][1]);
        if (C0) {
            float2 cc = *(const float2*)&C0[(r0 + u) * pc + c0];
            o.x += c0s * cc.x; o.y += c0s * cc.y;
        }
        *(float2*)&O[(r0 + u) * po + c0] = o;
    }
}

// ---------------- 64x64 SPD inverse via one-level Schur (in place) ---------
__device__ void inv64(float* M, int pm, float* ldacc,
                      float* w, float* t, float* u) {
    if (threadIdx.x < 32) gj32(M, pm, ldacc);               // a -> inva
    __syncthreads();
    sgemm32<false>(M + 32 * pm, pm, M, pm, w, P3, (const float*)0, 0, 0.f, 1.f);
    __syncthreads();
    sgemm32<false>(w, P3, M + 32, pm, t, P3, M + 32 * pm + 32, pm, 1.f, -1.f);
    __syncthreads();
    if (threadIdx.x < 32) gj32(t, P3, ldacc);               // t -> invt
    __syncthreads();
    sgemm32<false>(t, P3, w, P3, u, P3, (const float*)0, 0, 0.f, 1.f);
    __syncthreads();
    sgemm32<true>(w, P3, u, P3, M, pm, M, pm, 1.f, 1.f);    // TL = inva + w^T u
    for (int idx = threadIdx.x; idx < 1024; idx += 256) {
        int i = idx >> 5, j = idx & 31;
        M[(32 + i) * pm + 32 + j] = t[i * P3 + j];
        M[(32 + i) * pm + j]      = -u[i * P3 + j];
        M[i * pm + 32 + j]        = -u[j * P3 + i];
    }
    __syncthreads();
}

// ------- K2: per-class S^{-1}, log2det, tr(inv), w = inv·mu, pjj -----------
__global__ __launch_bounds__(256, 1) void k_sinv() {
    extern __shared__ float sm[];
    float* sS  = sm;                       // 128 * PL
    float* sW  = sS + KDIM * PL;           // 64 * PW
    float* sT  = sW + 64 * PW;
    float* sU  = sT + 64 * PW;
    float* s3a = sU + 64 * PW;             // 32 * P3 x3
    float* s3b = s3a + 32 * P3;
    float* s3c = s3b + 32 * P3;
    __shared__ float s_mu[KDIM];
    __shared__ float s_ld, s_tr, s_pjj;

    const int c = blockIdx.x, tid = threadIdx.x;

    float rn = 1.0f / (float)g_cnt[c];
    if (tid < KDIM) {
        float m = g_sum[c * KDIM + tid] * rn;
        s_mu[tid] = m;
        g_mu[c * KDIM + tid] = m;
    }
    if (tid == 0) { s_ld = 0.0f; s_tr = 0.0f; s_pjj = 0.0f; }
    __syncthreads();

    // build S = G/n - mu mu^T + I  (G lower triangle valid; mirror reads)
    const float* G = g_G + (size_t)c * MSZ;
    for (int idx = tid; idx < MSZ; idx += 256) {
        int a = idx >> 7, b = idx & 127;
        float g = (b <= a) ? G[idx] : G[b * KDIM + a];
        float s = g * rn - s_mu[a] * s_mu[b] + (a == b ? 1.0f : 0.0f);
        sS[a * PL + b] = s;
    }
    __syncthreads();

    float* Ig = g_inv + (size_t)c * MSZ;

    // ---- S = [[A, Bt],[B, C]] ; two-level Schur inverse ----
    inv64(sS, PL, &s_ld, s3a, s3b, s3c);                     // A -> invA
    sgemm64<false>(sS + 64 * PL, PL, sS, PL, sW, PW, (const float*)0, 0, 0.f, 1.f); // W = B·invA
    __syncthreads();
    sgemm64<false>(sW, PW, sS + 64, PL, sT, PW, sS + 64 * PL + 64, PL, 1.f, -1.f);  // T = C - W·B^T
    __syncthreads();
    inv64(sT, PW, &s_ld, s3a, s3b, s3c);                     // T -> invT
    sgemm64<false>(sT, PW, sW, PW, sU, PW, (const float*)0, 0, 0.f, 1.f);           // U = invT·W
    __syncthreads();
    // write the inverse straight to gmem: TL via GEMM, other blocks elementwise
    sgemm64<true>(sW, PW, sU, PW, Ig, KDIM, sS, PL, 1.f, 1.f);  // TL = invA + W^T·U
    for (int idx = tid; idx < 64 * 64; idx += 256) {
        int i = idx >> 6, j = idx & 63;
        float uv = sU[i * PW + j];
        Ig[(64 + i) * KDIM + 64 + j] = sT[i * PW + j];
        Ig[(64 + i) * KDIM + j]      = -uv;
        Ig[j * KDIM + 64 + i]        = -uv;
    }

    // trace of inverse: tr(invA) + <W,U>_F + tr(invT)   (all smem-resident)
    {
        float tp = 0.0f;
        for (int i = tid; i < 64; i += 256)
            tp += sS[i * PL + i] + sT[i * PW + i];
        for (int idx = tid; idx < 4096; idx += 256) {
            int i = idx >> 6, m = idx & 63;
            tp += sW[i * PW + m] * sU[i * PW + m];
        }
#pragma unroll
        for (int o = 16; o; o >>= 1) tp += __shfl_xor_sync(0xffffffffu, tp, o);
        if ((tid & 31) == 0) atomicAdd(&s_tr, tp);
    }
    __syncthreads();

    // w = inv · mu and pjj = mu·w  (rows are L1/L2-hot; float4 dots)
    float pv = 0.0f;
    if (tid < KDIM) {
        const float4* row = (const float4*)&Ig[tid * KDIM];
        float s = 0.0f;
#pragma unroll
        for (int q = 0; q < 32; q++) {
            float4 v = row[q];
            s += v.x * s_mu[q * 4] + v.y * s_mu[q * 4 + 1]
               + v.z * s_mu[q * 4 + 2] + v.w * s_mu[q * 4 + 3];
        }
        g_w[c * KDIM + tid] = s;
        pv = s * s_mu[tid];
    }
#pragma unroll
    for (int o = 16; o; o >>= 1) pv += __shfl_xor_sync(0xffffffffu, pv, o);
    if ((tid & 31) == 0) atomicAdd(&s_pjj, pv);
    __syncthreads();
    if (tid == 0) { g_ld2[c] = s_ld; g_trI[c] = s_tr; g_pjj[c] = s_pjj; }
}

// ------- K3: TRg[i][j] = <G_i, inv_j>/n_i -----------------------------------
// G is lower-tri (upper zeroed), so full Frobenius = 2*offdiag + diag.
__global__ __launch_bounds__(256) void k_tr() {
    extern __shared__ float sm[];
    float* sG = sm;                  // [k][cl] pitch PT, pre-weighted
    float* sI = sG + 128 * PT;
    __shared__ float s_rn[32];
    const int a0 = blockIdx.x;
    const int tid = threadIdx.x;

    if (tid < 32) s_rn[tid] = 1.0f / (float)g_cnt[tid];
    __syncthreads();

    for (int idx = tid; idx < 1024; idx += 256) {
        int cl = idx >> 5, q = idx & 31;
        int k = q << 2;
        float4 vg = *(const float4*)&g_G[(size_t)cl * MSZ + a0 * KDIM + k];
        float4 vi = *(const float4*)&g_inv[(size_t)cl * MSZ + a0 * KDIM + k];
        float rn = s_rn[cl];
        // weights: 2 for k<a0 (off-diag, counted twice), 1 for k==a0; k>a0 is 0 in G
        float w0 = (k     == a0) ? rn : 2.0f * rn;
        float w1 = (k + 1 == a0) ? rn : 2.0f * rn;
        float w2 = (k + 2 == a0) ? rn : 2.0f * rn;
        float w3 = (k + 3 == a0) ? rn : 2.0f * rn;
        sG[k * PT + cl] = vg.x * w0; sG[(k+1) * PT + cl] = vg.y * w1;
        sG[(k+2) * PT + cl] = vg.z * w2; sG[(k+3) * PT + cl] = vg.w * w3;
        sI[k * PT + cl] = vi.x; sI[(k+1) * PT + cl] = vi.y;
        sI[(k+2) * PT + cl] = vi.z; sI[(k+3) * PT + cl] = vi.w;
    }
    __syncthreads();

    const int i0 = (tid >> 4) * 2, j0 = (tid & 15) * 2;
    float t00 = 0, t01 = 0, t10 = 0, t11 = 0;
#pragma unroll 4
    for (int k = 0; k < 128; k++) {
        float b0 = sI[k * PT + j0], b1 = sI[k * PT + j0 + 1];
        float s0 = sG[k * PT + i0], s1 = sG[k * PT + i0 + 1];
        t00 = fmaf(s0, b0, t00); t01 = fmaf(s0, b1, t01);
        t10 = fmaf(s1, b0, t10); t11 = fmaf(s1, b1, t11);
    }
    atomicAdd(&g_TR[i0 * 32 + j0],           t00);
    atomicAdd(&g_TR[i0 * 32 + j0 + 1],       t01);
    atomicAdd(&g_TR[(i0 + 1) * 32 + j0],     t10);
    atomicAdd(&g_TR[(i0 + 1) * 32 + j0 + 1], t11);
}

// ------- K4: combine — R dots, mask, KL sum, -|mu|^2 ------------------------
// kl = 0.5*((ld2_j - ld2_i) - K - 2*mu_i.w_j + pjj[j] + TRg[i][j] + trI[j])
__global__ __launch_bounds__(256) void k_comb(float* __restrict__ out) {
    __shared__ float s_mu[32 * 128];
    __shared__ float s_w[32 * 129];
    __shared__ int   s_rank[32];
    __shared__ float s_part[8];
    const int tid = threadIdx.x;

    for (int idx = tid; idx < 1024; idx += 256) {
        int cl = idx >> 5, q = idx & 31;
        int k = q << 2;
        *(float4*)&s_mu[cl * 128 + k] = *(const float4*)&g_mu[cl * KDIM + k];
        float4 w = *(const float4*)&g_w[cl * KDIM + k];
        s_w[cl * 129 + k] = w.x; s_w[cl * 129 + k + 1] = w.y;
        s_w[cl * 129 + k + 2] = w.z; s_w[cl * 129 + k + 3] = w.w;
    }
    if (tid < 32) {
        int f = g_first[tid], r = 0;
        for (int c = 0; c < 32; c++) r += (g_first[c] < f);
        s_rank[tid] = r;
    }
    __syncthreads();

    const int pi = blockIdx.x * 256 + tid;     // pair 0..1023 (grid 4)
    const int i = pi >> 5, j = pi & 31;
    float acc = 0.0f;
    if (s_rank[i] <= CLS - 2 && s_rank[j] >= 1) {
        const float* mi = &s_mu[i * 128];
        const float* wj = &s_w[j * 129];
        float r = 0.0f;
#pragma unroll 8
        for (int k = 0; k < 128; k++) r = fmaf(mi[k], wj[k], r);
        acc = 0.5f * ((g_ld2[j] - g_ld2[i]) - (float)KDIM - 2.0f * r
                      + g_pjj[j] + g_TR[pi] + g_trI[j]);
    }
    if (blockIdx.x == 0) {
        float m2 = 0.0f;
        for (int t = tid; t < 4096; t += 256) { float m = s_mu[t]; m2 += m * m; }
        acc -= m2;
    }
#pragma unroll
    for (int o = 16; o; o >>= 1) acc += __shfl_xor_sync(0xffffffffu, acc, o);
    if ((tid & 31) == 0) s_part[tid >> 5] = acc;
    __syncthreads();
    if (tid == 0) {
        float s = 0.0f;
#pragma unroll
        for (int wp = 0; wp < 8; wp++) s += s_part[wp];
        atomicAdd(out, s);
    }
}

// ---------------- launch ----------------
extern "C" void kernel_launch(void* const* d_in, const int* in_sizes, int n_in,
                              void* d_out, int out_size) {
    const float* feat = (const float*)d_in[0];
    const int*   lab  = (const int*)d_in[1];
    float* out = (float*)d_out;

    const int SINV_SMEM = (KDIM * PL + 3 * 64 * PW + 3 * 32 * P3) * (int)sizeof(float);
    const int TR_SMEM   = 2 * 128 * PT * (int)sizeof(float);   // 33792
    cudaFuncSetAttribute(k_sinv, cudaFuncAttributeMaxDynamicSharedMemorySize, SINV_SMEM);
    cudaFuncSetAttribute(k_tr,   cudaFuncAttributeMaxDynamicSharedMemorySize, TR_SMEM);

    k_init<<<(CLS * MSZ + 255) / 256, 256>>>(out);
    k_scatter<<<dim3(RCHUNK, CLS), 256>>>(feat, lab);
    k_sinv<<<CLS, 256, SINV_SMEM>>>();
    k_tr<<<KDIM, 256, TR_SMEM>>>();             // capture position 4
    k_comb<<<4, 256>>>(out);
}

// round 16
// speedup vs baseline: 1.1004x; 1.1004x over previous
#include <cuda_runtime.h>
#include <math.h>

#define BATCH 16384
#define KDIM 128
#define CLS 32
#define PL 132             // sS pitch (%4==0)
#define PW 68              // 64-block pitch (%4==0)
#define P3 36              // 32-block pitch (%4==0)
#define PT 33              // k_tr staging pitch
#define RCHUNK 8
#define RPC (BATCH / RCHUNK)   // 2048
#define MSZ (KDIM * KDIM)      // 16384

// ---------------- scratch (device globals: allocation-free) ----------------
__device__ float g_sum[CLS * KDIM];
__device__ int   g_cnt[CLS];
__device__ int   g_first[CLS];
__device__ float g_G[CLS * MSZ];       // lower triangle valid; upper stays 0
__device__ float g_inv[CLS * MSZ];
__device__ float g_mu[CLS * KDIM];
__device__ float g_w[CLS * KDIM];      // w_c = inv_c · mu_c
__device__ float g_ld2[CLS];
__device__ float g_trI[CLS];           // tr(inv_c)
__device__ float g_pjj[CLS];           // mu_c^T inv_c mu_c
__device__ float g_TR[CLS * CLS];      // <G_i, inv_j>/n_i

// ---------------- K0: zero all scratch + output ----------------
__global__ void k_init(float* out) {
    int i = blockIdx.x * blockDim.x + threadIdx.x;
    if (i < CLS * MSZ) g_G[i] = 0.0f;
    if (i < CLS * KDIM) g_sum[i] = 0.0f;
    if (i < CLS * CLS) g_TR[i] = 0.0f;
    if (i < CLS) { g_cnt[i] = 0; g_first[i] = BATCH; }
    if (i == 0) out[0] = 0.0f;
}

// ------- K1: per-class Gram (atomic, lower tri) + fused sums/count/first ---
// Column mapping tx+16v: b-loads are 16-consecutive floats -> conflict-free.
__global__ __launch_bounds__(256) void k_scatter(const float* __restrict__ feat,
                                                 const int* __restrict__ lab) {
    const int c = blockIdx.y;
    const int chunk = blockIdx.x;
    const int R0 = chunk * RPC;
    __shared__ int s_idx[RPC];
    __shared__ int s_n, s_min;
    __shared__ __align__(16) float s_x[16][KDIM];
    const int tid = threadIdx.x;
    if (tid == 0) { s_n = 0; s_min = BATCH; }
    __syncthreads();

    for (int r = R0 + tid; r < R0 + RPC; r += 256) {
        if (lab[r] == c) {
            int p = atomicAdd(&s_n, 1);
            s_idx[p] = r;
            atomicMin(&s_min, r);
        }
    }
    __syncthreads();
    const int n = s_n;
    if (n == 0) return;

    float acc[8][8];
#pragma unroll
    for (int u = 0; u < 8; u++)
#pragma unroll
        for (int v = 0; v < 8; v++) acc[u][v] = 0.0f;
    float csum = 0.0f;

    const int ty = tid >> 4, tx = tid & 15;

    for (int t = 0; t < n; t += 16) {
        int m = min(16, n - t);
        for (int i = tid; i < m * 32; i += 256) {
            int rr = i >> 5, q = i & 31;
            ((float4*)s_x[rr])[q] =
                ((const float4*)(feat + (size_t)s_idx[t + rr] * KDIM))[q];
        }
        __syncthreads();
        if (tid < KDIM)
            for (int e = 0; e < m; e++) csum += s_x[e][tid];
        for (int e = 0; e < m; e++) {
            float a[8], b[8];
#pragma unroll
            for (int u = 0; u < 8; u++) { a[u] = s_x[e][ty * 8 + u]; b[u] = s_x[e][tx + 16 * u]; }
#pragma unroll
            for (int u = 0; u < 8; u++)
#pragma unroll
                for (int v = 0; v < 8; v++) acc[u][v] = fmaf(a[u], b[v], acc[u][v]);
        }
        __syncthreads();
    }

    // lower triangle only (col <= row) — halves global atomic traffic
    float* G = g_G + (size_t)c * MSZ;
#pragma unroll
    for (int u = 0; u < 8; u++) {
        int row = ty * 8 + u;
#pragma unroll
        for (int v = 0; v < 8; v++) {
            int col = tx + 16 * v;
            if (col <= row)
                atomicAdd(&G[row * KDIM + col], acc[u][v]);
        }
    }

    if (tid < KDIM) atomicAdd(&g_sum[c * KDIM + tid], csum);
    if (tid == 0) { atomicAdd(&g_cnt[c], n); atomicMin(&g_first[c], s_min); }
}

// ---------------- warp Gauss-Jordan inverse of SPD 32x32 (in-place) --------
__device__ __forceinline__ void gj32(float* M, int P, float* ldacc) {
    const int lane = threadIdx.x & 31;
    float y[32];
#pragma unroll
    for (int m = 0; m < 32; m++) y[m] = M[lane * P + m];
    float ld = 0.0f;
#pragma unroll
    for (int j = 0; j < 32; j++) {
        float pj = __shfl_sync(0xffffffffu, y[j], j);
        float r = __fdividef(1.0f, pj);
        float c = y[j];
        if (lane == j) {
            ld = log2f(pj);
#pragma unroll
            for (int m = 0; m < 32; m++) y[m] *= r;
            y[j] = r;
        }
#pragma unroll
        for (int m = 0; m < 32; m++) {
            float rowj = __shfl_sync(0xffffffffu, y[m], j);
            if (lane != j && m != j) y[m] -= c * rowj;
        }
        if (lane != j) y[j] = -c * r;
    }
#pragma unroll
    for (int m = 0; m < 32; m++) M[lane * P + m] = y[m];
#pragma unroll
    for (int o = 16; o; o >>= 1) ld += __shfl_xor_sync(0xffffffffu, ld, o);
    if (lane == 0) *ldacc += ld;
}

// ------ 64-GEMM (256 thr, 4x4 tiles): O = c0s*C0 + sgn*op(P)·Q -------------
template<bool TRA>
__device__ __forceinline__ void sgemm64(const float* __restrict__ P, int pp,
                                        const float* __restrict__ Q, int pq,
                                        float* __restrict__ O, int po,
                                        const float* __restrict__ C0, int pc,
                                        float c0s, float sgn) {
    const int r0 = (threadIdx.x >> 4) * 4;
    const int c0 = (threadIdx.x & 15) * 4;
    float acc[4][4];
#pragma unroll
    for (int u = 0; u < 4; u++)
#pragma unroll
        for (int v = 0; v < 4; v++) acc[u][v] = 0.0f;
#pragma unroll 4
    for (int m = 0; m < 64; m++) {
        float4 b = *(const float4*)&Q[m * pq + c0];
        float a[4];
        if (TRA) {
            float4 t = *(const float4*)&P[m * pp + r0];
            a[0] = t.x; a[1] = t.y; a[2] = t.z; a[3] = t.w;
        } else {
#pragma unroll
            for (int u = 0; u < 4; u++) a[u] = P[(r0 + u) * pp + m];
        }
#pragma unroll
        for (int u = 0; u < 4; u++) {
            acc[u][0] = fmaf(a[u], b.x, acc[u][0]);
            acc[u][1] = fmaf(a[u], b.y, acc[u][1]);
            acc[u][2] = fmaf(a[u], b.z, acc[u][2]);
            acc[u][3] = fmaf(a[u], b.w, acc[u][3]);
        }
    }
#pragma unroll
    for (int u = 0; u < 4; u++) {
        float4 o = make_float4(sgn * acc[u][0], sgn * acc[u][1],
                               sgn * acc[u][2], sgn * acc[u][3]);
        if (C0) {
            float4 cc = *(const float4*)&C0[(r0 + u) * pc + c0];
            o.x += c0s * cc.x; o.y += c0s * cc.y;
            o.z += c0s * cc.z; o.w += c0s * cc.w;
        }
        *(float4*)&O[(r0 + u) * po + c0] = o;
    }
}

// ------ 32-GEMM (256 thr, 2x2 tiles) ----------------------------------------
template<bool TRA>
__device__ __forceinline__ void sgemm32(const float* __restrict__ P, int pp,
                                        const float* __restrict__ Q, int pq,
                                        float* __restrict__ O, int po,
                                        const float* __restrict__ C0, int pc,
                                        float c0s, float sgn) {
    const int r0 = (threadIdx.x >> 4) * 2;
    const int c0 = (threadIdx.x & 15) * 2;
    float acc[2][2] = {{0.f, 0.f}, {0.f, 0.f}};
#pragma unroll 8
    for (int m = 0; m < 32; m++) {
        float2 b = *(const float2*)&Q[m * pq + c0];
        float a0 = TRA ? P[m * pp + r0]     : P[r0 * pp + m];
        float a1 = TRA ? P[m * pp + r0 + 1] : P[(r0 + 1) * pp + m];
        acc[0][0] = fmaf(a0, b.x, acc[0][0]); acc[0][1] = fmaf(a0, b.y, acc[0][1]);
        acc[1][0] = fmaf(a1, b.x, acc[1][0]); acc[1][1] = fmaf(a1, b.y, acc[1][1]);
    }
#pragma unroll
    for (int u = 0; u < 2; u++) {
        float2 o = make_float2(sgn * acc[u][0], sgn * acc[u][1]);
        if (C0) {
            float2 cc = *(const float2*)&C0[(r0 + u) * pc + c0];
            o.x += c0s * cc.x; o.y += c0s * cc.y;
        }
        *(float2*)&O[(r0 + u) * po + c0] = o;
    }
}

// ---------------- 64x64 SPD inverse via one-level Schur (in place) ---------
__device__ void inv64(float* M, int pm, float* ldacc,
                      float* w, float* t, float* u) {
    if (threadIdx.x < 32) gj32(M, pm, ldacc);               // a -> inva
    __syncthreads();
    sgemm32<false>(M + 32 * pm, pm, M, pm, w, P3, (const float*)0, 0, 0.f, 1.f);
    __syncthreads();
    sgemm32<false>(w, P3, M + 32, pm, t, P3, M + 32 * pm + 32, pm, 1.f, -1.f);
    __syncthreads();
    if (threadIdx.x < 32) gj32(t, P3, ldacc);               // t -> invt
    __syncthreads();
    sgemm32<false>(t, P3, w, P3, u, P3, (const float*)0, 0, 0.f, 1.f);
    __syncthreads();
    sgemm32<true>(w, P3, u, P3, M, pm, M, pm, 1.f, 1.f);    // TL = inva + w^T u
    for (int idx = threadIdx.x; idx < 1024; idx += 256) {
        int i = idx >> 5, j = idx & 31;
        M[(32 + i) * pm + 32 + j] = t[i * P3 + j];
        M[(32 + i) * pm + j]      = -u[i * P3 + j];
        M[i * pm + 32 + j]        = -u[j * P3 + i];
    }
    __syncthreads();
}

// ------- K2: per-class S^{-1}, log2det, tr(inv), w = inv·mu, pjj -----------
__global__ __launch_bounds__(256, 1) void k_sinv() {
    extern __shared__ float sm[];
    float* sS  = sm;                       // 128 * PL
    float* sW  = sS + KDIM * PL;           // 64 * PW
    float* sT  = sW + 64 * PW;
    float* sU  = sT + 64 * PW;
    float* s3a = sU + 64 * PW;             // 32 * P3 x3
    float* s3b = s3a + 32 * P3;
    float* s3c = s3b + 32 * P3;
    __shared__ float s_mu[KDIM];
    __shared__ float s_ld, s_tr, s_pjj;

    const int c = blockIdx.x, tid = threadIdx.x;

    float rn = 1.0f / (float)g_cnt[c];
    if (tid < KDIM) {
        float m = g_sum[c * KDIM + tid] * rn;
        s_mu[tid] = m;
        g_mu[c * KDIM + tid] = m;
    }
    if (tid == 0) { s_ld = 0.0f; s_tr = 0.0f; s_pjj = 0.0f; }
    __syncthreads();

    // build S = G/n - mu mu^T + I  (G lower triangle valid; mirror reads)
    const float* G = g_G + (size_t)c * MSZ;
    for (int idx = tid; idx < MSZ; idx += 256) {
        int a = idx >> 7, b = idx & 127;
        float g = (b <= a) ? G[idx] : G[b * KDIM + a];
        float s = g * rn - s_mu[a] * s_mu[b] + (a == b ? 1.0f : 0.0f);
        sS[a * PL + b] = s;
    }
    __syncthreads();

    float* Ig = g_inv + (size_t)c * MSZ;

    // ---- S = [[A, Bt],[B, C]] ; two-level Schur inverse ----
    inv64(sS, PL, &s_ld, s3a, s3b, s3c);                     // A -> invA
    sgemm64<false>(sS + 64 * PL, PL, sS, PL, sW, PW, (const float*)0, 0, 0.f, 1.f); // W = B·invA
    __syncthreads();
    sgemm64<false>(sW, PW, sS + 64, PL, sT, PW, sS + 64 * PL + 64, PL, 1.f, -1.f);  // T = C - W·B^T
    __syncthreads();
    inv64(sT, PW, &s_ld, s3a, s3b, s3c);                     // T -> invT
    sgemm64<false>(sT, PW, sW, PW, sU, PW, (const float*)0, 0, 0.f, 1.f);           // U = invT·W
    __syncthreads();
    // write the inverse straight to gmem: TL via GEMM, other blocks elementwise
    sgemm64<true>(sW, PW, sU, PW, Ig, KDIM, sS, PL, 1.f, 1.f);  // TL = invA + W^T·U
    for (int idx = tid; idx < 64 * 64; idx += 256) {
        int i = idx >> 6, j = idx & 63;
        float uv = sU[i * PW + j];
        Ig[(64 + i) * KDIM + 64 + j] = sT[i * PW + j];
        Ig[(64 + i) * KDIM + j]      = -uv;
        Ig[j * KDIM + 64 + i]        = -uv;
    }

    // trace of inverse: tr(invA) + <W,U>_F + tr(invT)   (all smem-resident)
    {
        float tp = 0.0f;
        for (int i = tid; i < 64; i += 256)
            tp += sS[i * PL + i] + sT[i * PW + i];
        for (int idx = tid; idx < 4096; idx += 256) {
            int i = idx >> 6, m = idx & 63;
            tp += sW[i * PW + m] * sU[i * PW + m];
        }
#pragma unroll
        for (int o = 16; o; o >>= 1) tp += __shfl_xor_sync(0xffffffffu, tp, o);
        if ((tid & 31) == 0) atomicAdd(&s_tr, tp);
    }
    __syncthreads();

    // w = inv · mu and pjj = mu·w  (rows are L1/L2-hot; float4 dots)
    float pv = 0.0f;
    if (tid < KDIM) {
        const float4* row = (const float4*)&Ig[tid * KDIM];
        float s = 0.0f;
#pragma unroll
        for (int q = 0; q < 32; q++) {
            float4 v = row[q];
            s += v.x * s_mu[q * 4] + v.y * s_mu[q * 4 + 1]
               + v.z * s_mu[q * 4 + 2] + v.w * s_mu[q * 4 + 3];
        }
        g_w[c * KDIM + tid] = s;
        pv = s * s_mu[tid];
    }
#pragma unroll
    for (int o = 16; o; o >>= 1) pv += __shfl_xor_sync(0xffffffffu, pv, o);
    if ((tid & 31) == 0) atomicAdd(&s_pjj, pv);
    __syncthreads();
    if (tid == 0) { g_ld2[c] = s_ld; g_trI[c] = s_tr; g_pjj[c] = s_pjj; }
}

// ------- K3: TRg[i][j] = <G_i, inv_j>/n_i -----------------------------------
// Tiles (i0,i0+16)x(j0,j0+16): all four operand loads conflict-free.
__global__ __launch_bounds__(256) void k_tr() {
    extern __shared__ float sm[];
    float* sG = sm;                  // [k][cl] pitch PT, pre-weighted
    float* sI = sG + 128 * PT;
    __shared__ float s_rn[32];
    const int a0 = blockIdx.x;
    const int tid = threadIdx.x;

    if (tid < 32) s_rn[tid] = 1.0f / (float)g_cnt[tid];
    __syncthreads();

    for (int idx = tid; idx < 1024; idx += 256) {
        int cl = idx >> 5, q = idx & 31;
        int k = q << 2;
        float4 vg = *(const float4*)&g_G[(size_t)cl * MSZ + a0 * KDIM + k];
        float4 vi = *(const float4*)&g_inv[(size_t)cl * MSZ + a0 * KDIM + k];
        float rn = s_rn[cl];
        // weights: 2 for k<a0 (off-diag, counted twice), 1 for k==a0; k>a0 is 0 in G
        float w0 = (k     == a0) ? rn : 2.0f * rn;
        float w1 = (k + 1 == a0) ? rn : 2.0f * rn;
        float w2 = (k + 2 == a0) ? rn : 2.0f * rn;
        float w3 = (k + 3 == a0) ? rn : 2.0f * rn;
        sG[k * PT + cl] = vg.x * w0; sG[(k+1) * PT + cl] = vg.y * w1;
        sG[(k+2) * PT + cl] = vg.z * w2; sG[(k+3) * PT + cl] = vg.w * w3;
        sI[k * PT + cl] = vi.x; sI[(k+1) * PT + cl] = vi.y;
        sI[(k+2) * PT + cl] = vi.z; sI[(k+3) * PT + cl] = vi.w;
    }
    __syncthreads();

    const int i0 = tid >> 4;      // rows i0, i0+16
    const int j0 = tid & 15;      // cols j0, j0+16
    float t00 = 0, t01 = 0, t10 = 0, t11 = 0;
#pragma unroll 4
    for (int k = 0; k < 128; k++) {
        float b0 = sI[k * PT + j0], b1 = sI[k * PT + j0 + 16];
        float s0 = sG[k * PT + i0], s1 = sG[k * PT + i0 + 16];
        t00 = fmaf(s0, b0, t00); t01 = fmaf(s0, b1, t01);
        t10 = fmaf(s1, b0, t10); t11 = fmaf(s1, b1, t11);
    }
    atomicAdd(&g_TR[i0 * 32 + j0],             t00);
    atomicAdd(&g_TR[i0 * 32 + j0 + 16],        t01);
    atomicAdd(&g_TR[(i0 + 16) * 32 + j0],      t10);
    atomicAdd(&g_TR[(i0 + 16) * 32 + j0 + 16], t11);
}

// ------- K4: combine — R dots, mask, KL sum, -|mu|^2 ------------------------
// kl = 0.5*((ld2_j - ld2_i) - K - 2*mu_i.w_j + pjj[j] + TRg[i][j] + trI[j])
__global__ __launch_bounds__(256) void k_comb(float* __restrict__ out) {
    __shared__ float s_mu[32 * 128];
    __shared__ float s_w[32 * 129];
    __shared__ int   s_rank[32];
    __shared__ float s_part[8];
    const int tid = threadIdx.x;

    for (int idx = tid; idx < 1024; idx += 256) {
        int cl = idx >> 5, q = idx & 31;
        int k = q << 2;
        *(float4*)&s_mu[cl * 128 + k] = *(const float4*)&g_mu[cl * KDIM + k];
        float4 w = *(const float4*)&g_w[cl * KDIM + k];
        s_w[cl * 129 + k] = w.x; s_w[cl * 129 + k + 1] = w.y;
        s_w[cl * 129 + k + 2] = w.z; s_w[cl * 129 + k + 3] = w.w;
    }
    if (tid < 32) {
        int f = g_first[tid], r = 0;
        for (int c = 0; c < 32; c++) r += (g_first[c] < f);
        s_rank[tid] = r;
    }
    __syncthreads();

    const int pi = blockIdx.x * 256 + tid;     // pair 0..1023 (grid 4)
    const int i = pi >> 5, j = pi & 31;
    float acc = 0.0f;
    if (s_rank[i] <= CLS - 2 && s_rank[j] >= 1) {
        const float* mi = &s_mu[i * 128];
        const float* wj = &s_w[j * 129];
        float r = 0.0f;
#pragma unroll 8
        for (int k = 0; k < 128; k++) r = fmaf(mi[k], wj[k], r);
        acc = 0.5f * ((g_ld2[j] - g_ld2[i]) - (float)KDIM - 2.0f * r
                      + g_pjj[j] + g_TR[pi] + g_trI[j]);
    }
    if (blockIdx.x == 0) {
        float m2 = 0.0f;
        for (int t = tid; t < 4096; t += 256) { float m = s_mu[t]; m2 += m * m; }
        acc -= m2;
    }
#pragma unroll
    for (int o = 16; o; o >>= 1) acc += __shfl_xor_sync(0xffffffffu, acc, o);
    if ((tid & 31) == 0) s_part[tid >> 5] = acc;
    __syncthreads();
    if (tid == 0) {
        float s = 0.0f;
#pragma unroll
        for (int wp = 0; wp < 8; wp++) s += s_part[wp];
        atomicAdd(out, s);
    }
}

// ---------------- launch ----------------
extern "C" void kernel_launch(void* const* d_in, const int* in_sizes, int n_in,
                              void* d_out, int out_size) {
    const float* feat = (const float*)d_in[0];
    const int*   lab  = (const int*)d_in[1];
    float* out = (float*)d_out;

    const int SINV_SMEM = (KDIM * PL + 3 * 64 * PW + 3 * 32 * P3) * (int)sizeof(float);
    const int TR_SMEM   = 2 * 128 * PT * (int)sizeof(float);   // 33792
    cudaFuncSetAttribute(k_sinv, cudaFuncAttributeMaxDynamicSharedMemorySize, SINV_SMEM);
    cudaFuncSetAttribute(k_tr,   cudaFuncAttributeMaxDynamicSharedMemorySize, TR_SMEM);

    k_init<<<(CLS * MSZ + 255) / 256, 256>>>(out);
    k_scatter<<<dim3(RCHUNK, CLS), 256>>>(feat, lab);   // capture position 2
    k_sinv<<<CLS, 256, SINV_SMEM>>>();
    k_tr<<<KDIM, 256, TR_SMEM>>>();
    k_comb<<<4, 256>>>(out);
}